// round 6
// baseline (speedup 1.0000x reference)
#include <cuda_runtime.h>
#include <math.h>

#define NB 4
#define CC 64
#define WW 400
#define HWN (WW*WW)          // 160000
#define TS 32
#define CPB 32               // channels per pass_b block (z-split 2)
#define NSTG 2               // channels per pipeline stage-group
#define NGRP (CPB/NSTG)      // 16
#define NBUF 3               // pipeline depth
#define FAST_TAG 0x40000000

// Scratch (allocation-free rule). Zero-init at load; reset_kernel restores
// g_winner to zeros after pass_b consumes it (deterministic per replay).
__device__ int   g_winner[NB*HWN];   // winner_idx+1; 0 = no winner
__device__ float g_a[NB*HWN];
__device__ float g_b[NB*HWN];

__global__ void __launch_bounds__(256) reset_kernel() {
    int i = blockIdx.x * blockDim.x + threadIdx.x;   // 625*256 = NB*HWN/4
    ((int4*)g_winner)[i] = make_int4(0, 0, 0, 0);
}

__device__ __forceinline__ void cp16(void* smem, const void* g) {
    unsigned s = (unsigned)__cvta_generic_to_shared(smem);
    asm volatile("cp.async.cg.shared.global [%0], [%1], 16;" :: "r"(s), "l"(g));
}
// swizzled scalar offset within a 32x32 tile (float units)
__device__ __forceinline__ int swz(int r, int c) {
    return r * 32 + ((((c >> 2) ^ (r >> 2)) & 7) << 2) + (c & 3);
}

// ---------------------------------------------------------------------------
// Pass A: 1x1 convs -> offsets -> scatter (atomicMax(idx+1) = last-write-wins),
// store blend coeffs. float4 over 4 consecutive pixels; full unroll for MLP.
// ---------------------------------------------------------------------------
__global__ void __launch_bounds__(256) pass_a(const float* __restrict__ feat,
                                              const float* __restrict__ wc,
                                              const float* __restrict__ ws,
                                              const float* __restrict__ wp) {
    __shared__ float swc0[CC], swc1[CC], sws0[CC], sws1[CC], swp[CC];
    int t = threadIdx.x;
    if (t < CC) {
        swc0[t] = wc[t];      swc1[t] = wc[CC + t];
        sws0[t] = ws[t];      sws1[t] = ws[CC + t];
        swp[t]  = wp[t];
    }
    __syncthreads();

    int p4 = blockIdx.x * blockDim.x + t;
    if (p4 >= HWN/4) return;
    int n = blockIdx.y;
    const float4* f4 = (const float4*)(feat + (size_t)n * CC * HWN);

    float c0[4] = {0,0,0,0}, c1[4] = {0,0,0,0};
    float s0[4] = {0,0,0,0}, s1[4] = {0,0,0,0}, pv[4] = {0,0,0,0};
#pragma unroll 16
    for (int c = 0; c < CC; c++) {
        float4 v = __ldg(&f4[(size_t)c * (HWN/4) + p4]);
        float a0 = swc0[c], a1 = swc1[c], b0 = sws0[c], b1 = sws1[c], pw = swp[c];
        c0[0] = fmaf(v.x, a0, c0[0]); c0[1] = fmaf(v.y, a0, c0[1]);
        c0[2] = fmaf(v.z, a0, c0[2]); c0[3] = fmaf(v.w, a0, c0[3]);
        c1[0] = fmaf(v.x, a1, c1[0]); c1[1] = fmaf(v.y, a1, c1[1]);
        c1[2] = fmaf(v.z, a1, c1[2]); c1[3] = fmaf(v.w, a1, c1[3]);
        s0[0] = fmaf(v.x, b0, s0[0]); s0[1] = fmaf(v.y, b0, s0[1]);
        s0[2] = fmaf(v.z, b0, s0[2]); s0[3] = fmaf(v.w, b0, s0[3]);
        s1[0] = fmaf(v.x, b1, s1[0]); s1[1] = fmaf(v.y, b1, s1[1]);
        s1[2] = fmaf(v.z, b1, s1[2]); s1[3] = fmaf(v.w, b1, s1[3]);
        pv[0] = fmaf(v.x, pw, pv[0]); pv[1] = fmaf(v.y, pw, pv[1]);
        pv[2] = fmaf(v.z, pw, pv[2]); pv[3] = fmaf(v.w, pw, pv[3]);
    }

    float4 av, bv;
    float* avp = &av.x; float* bvp = &bv.x;
#pragma unroll
    for (int m = 0; m < 4; m++) {
        int idx = p4 * 4 + m;
        float st0 = fmaxf(s0[m], 0.f), st1 = fmaxf(s1[m], 0.f);
        float pr = 1.f / (1.f + expf(-pv[m]));
        int i = idx / WW, j = idx - (idx / WW) * WW;
        float th = fminf(rintf((float)i + c0[m] * st0), (float)(WW - 1));
        float tw = fminf(rintf((float)j + c1[m] * st1), (float)(WW - 1));
        int tt = (int)(th * (float)WW + tw);
        tt %= HWN; if (tt < 0) tt += HWN;        // python-style mod
        atomicMax(&g_winner[n * HWN + tt], idx + 1);
        float q = 1.f - pr;
        avp[m] = pr + q * q;
        bvp[m] = pr * q;
    }
    ((float4*)g_a)[(size_t)n * (HWN/4) + p4] = av;
    ((float4*)g_b)[(size_t)n * (HWN/4) + p4] = bv;
}

// ---------------------------------------------------------------------------
// Pass B: mirror-tile pairs + cp.async TRIPLE-buffered channel pipeline.
// Block (bx,by), by<=bx, z = n*2 + channel-half. Output tiles:
//   A: rows [aR..) x cols [aC..)    B: mirror (skipped when diagonal)
// Staged tile A is f-source for A and gather source for B (and vice versa).
// Tiles stored with float4-slot XOR swizzle: 16B-aligned for cp.async AND
// conflict-free for both row-major f-reads and transpose-pattern gathers.
// ---------------------------------------------------------------------------
__global__ void __launch_bounds__(256) pass_b(const float* __restrict__ feat,
                                              float* __restrict__ out) {
    __shared__ float sbuf[NBUF][NSTG][2][TS*TS]; // [buf][stage-ch][tile A/B][swz]

    int bx = blockIdx.x, by = blockIdx.y;
    if (by > bx) return;
    bool diag = (bx == by);
    int zc = blockIdx.z;
    int n = zc >> 1;
    int cbase = (zc & 1) * CPB;

    int aR = by * TS, aC = bx * TS;
    int ah = min(TS, WW - aR), aw = min(TS, WW - aC);   // 32 or 16

    int tid = threadIdx.x;
    int trow = tid >> 3, tq = tid & 7, tc0 = tq * 4;
    int slotoff = trow * 32 + ((tq ^ (trow >> 2)) & 7) * 4;

    const float* fb = feat + (size_t)n * CC * HWN;
    float*       ob = out  + (size_t)n * CC * HWN;
    const int*   wn = g_winner + n * HWN;
    const float* ga = g_a + n * HWN;
    const float* gb = g_b + n * HWN;

    bool aval = (trow < ah) && (tc0 < aw);
    bool bval = (!diag) && (trow < aw) && (tc0 < ah);

    // ---- metadata (registers), read-only ----
    int gA[4]; float4 cAa, cAb;
    if (aval) {
        int idx = (aR + trow) * WW + aC + tc0;
        int4 w4 = *(const int4*)(wn + idx);
        cAa = *(const float4*)(ga + idx);
        cAb = *(const float4*)(gb + idx);
        int wv[4] = {w4.x, w4.y, w4.z, w4.w};
#pragma unroll
        for (int m = 0; m < 4; m++) {
            int src = (wv[m] > 0) ? (wv[m] - 1) : (idx + m);
            int sh = src / WW, sw = src - sh * WW;       // sampled = feat[sw][sh]
            int lr = sw - aC, lc = sh - aR;              // into B region
            gA[m] = ((unsigned)lr < (unsigned)aw && (unsigned)lc < (unsigned)ah)
                    ? swz(lr, lc)
                    : (FAST_TAG | (sw * WW + sh));
        }
    }
    int gB[4]; float4 cBa, cBb;
    if (bval) {
        int idx = (aC + trow) * WW + aR + tc0;
        int4 w4 = *(const int4*)(wn + idx);
        cBa = *(const float4*)(ga + idx);
        cBb = *(const float4*)(gb + idx);
        int wv[4] = {w4.x, w4.y, w4.z, w4.w};
#pragma unroll
        for (int m = 0; m < 4; m++) {
            int src = (wv[m] > 0) ? (wv[m] - 1) : (idx + m);
            int sh = src / WW, sw = src - sh * WW;
            int lr = sw - aR, lc = sh - aC;              // into A region
            gB[m] = ((unsigned)lr < (unsigned)ah && (unsigned)lc < (unsigned)aw)
                    ? swz(lr, lc)
                    : (FAST_TAG | (sw * WW + sh));
        }
    }

    auto stage = [&](int g) {
        int b = g % NBUF;
#pragma unroll
        for (int s = 0; s < NSTG; s++) {
            const float* fp = fb + (size_t)(cbase + g * NSTG + s) * HWN;
            if (aval) cp16(&sbuf[b][s][0][slotoff], fp + (aR + trow) * WW + aC + tc0);
            if (bval) cp16(&sbuf[b][s][1][slotoff], fp + (aC + trow) * WW + aR + tc0);
        }
        asm volatile("cp.async.commit_group;");
    };

    stage(0); stage(1); stage(2);

    for (int g = 0; g < NGRP; g++) {
        int b = g % NBUF;
        if (g + 3 <= NGRP)      asm volatile("cp.async.wait_group 2;");
        else if (g + 2 == NGRP) asm volatile("cp.async.wait_group 1;");
        else                    asm volatile("cp.async.wait_group 0;");
        __syncthreads();

#pragma unroll
        for (int s = 0; s < NSTG; s++) {
            int ch = cbase + g * NSTG + s;
            const float* fp = fb + (size_t)ch * HWN;
            float*       op = ob + (size_t)ch * HWN;
            const float* tA = sbuf[b][s][0];
            const float* tB = sbuf[b][s][1];
            if (aval) {
                const float* gsrc = diag ? tA : tB;
                float4 f = *(const float4*)(tA + slotoff);
                const float* fx = &f.x;
                const float* ca = &cAa.x; const float* cb = &cAb.x;
                float4 o; float* ox = &o.x;
#pragma unroll
                for (int m = 0; m < 4; m++) {
                    int gi = gA[m];
                    float sval = (gi & FAST_TAG) ? __ldg(fp + (gi & (FAST_TAG-1)))
                                                 : gsrc[gi];
                    ox[m] = ca[m] * fx[m] + cb[m] * sval;
                }
                *(float4*)(op + (aR + trow) * WW + aC + tc0) = o;
            }
            if (bval) {
                float4 f = *(const float4*)(tB + slotoff);
                const float* fx = &f.x;
                const float* ca = &cBa.x; const float* cb = &cBb.x;
                float4 o; float* ox = &o.x;
#pragma unroll
                for (int m = 0; m < 4; m++) {
                    int gi = gB[m];
                    float sval = (gi & FAST_TAG) ? __ldg(fp + (gi & (FAST_TAG-1)))
                                                 : tA[gi];
                    ox[m] = ca[m] * fx[m] + cb[m] * sval;
                }
                *(float4*)(op + (aC + trow) * WW + aR + tc0) = o;
            }
        }
        __syncthreads();
        if (g + 3 < NGRP) stage(g + 3);
    }
}

extern "C" void kernel_launch(void* const* d_in, const int* in_sizes, int n_in,
                              void* d_out, int out_size) {
    const float* feat = (const float*)d_in[0];
    const float* wc   = (const float*)d_in[1];
    const float* ws   = (const float*)d_in[2];
    const float* wp   = (const float*)d_in[3];
    float* out = (float*)d_out;

    pass_a<<<dim3((HWN/4 + 255) / 256, NB), 256>>>(feat, wc, ws, wp);
    pass_b<<<dim3((WW + TS - 1) / TS, (WW + TS - 1) / TS, NB * 2), 256>>>(feat, out);
    reset_kernel<<<NB*HWN/4/256, 256>>>();
}

// round 7
// speedup vs baseline: 1.0887x; 1.0887x over previous
#include <cuda_runtime.h>
#include <math.h>

#define NB 4
#define CC 64
#define WW 400
#define HWN (WW*WW)          // 160000
#define TS 32
#define CPB 32               // channels per pass_b block (z-split 2)
#define NSTG 2               // channels per pipeline stage-group
#define NGRP (CPB/NSTG)      // 16
#define FAST_TAG 0x40000000
#define NTILE 13             // ceil(400/32)
#define NPAIR (NTILE*(NTILE+1)/2)   // 91 triangular tile-pairs

// Scratch (allocation-free rule). Zero-init at load; reset_kernel restores
// g_winner to zeros after pass_b consumes it (deterministic per replay).
__device__ int   g_winner[NB*HWN];   // winner_idx+1; 0 = no winner
__device__ float g_a[NB*HWN];
__device__ float g_b[NB*HWN];

__global__ void __launch_bounds__(256) reset_kernel() {
    int i = blockIdx.x * blockDim.x + threadIdx.x;   // 625*256 = NB*HWN/4
    ((int4*)g_winner)[i] = make_int4(0, 0, 0, 0);
}

__device__ __forceinline__ void cp16(void* smem, const void* g) {
    unsigned s = (unsigned)__cvta_generic_to_shared(smem);
    asm volatile("cp.async.cg.shared.global [%0], [%1], 16;" :: "r"(s), "l"(g));
}
// swizzled scalar offset within a 32x32 tile (float units)
__device__ __forceinline__ int swz(int r, int c) {
    return r * 32 + ((((c >> 2) ^ (r >> 2)) & 7) << 2) + (c & 3);
}

// ---------------------------------------------------------------------------
// Pass A: 1x1 convs -> offsets -> scatter (atomicMax(idx+1) = last-write-wins),
// store blend coeffs. float4 over 4 consecutive pixels.
// Grid-stride over NB*HWN/4 items with grid = 148*4 blocks for wave balance.
// ---------------------------------------------------------------------------
#define PA_BLOCKS 592
__global__ void __launch_bounds__(256) pass_a(const float* __restrict__ feat,
                                              const float* __restrict__ wc,
                                              const float* __restrict__ ws,
                                              const float* __restrict__ wp) {
    __shared__ float swc0[CC], swc1[CC], sws0[CC], sws1[CC], swp[CC];
    int t = threadIdx.x;
    if (t < CC) {
        swc0[t] = wc[t];      swc1[t] = wc[CC + t];
        sws0[t] = ws[t];      sws1[t] = ws[CC + t];
        swp[t]  = wp[t];
    }
    __syncthreads();

    const int total = NB * (HWN/4);
    for (int item = blockIdx.x * blockDim.x + t; item < total;
         item += PA_BLOCKS * 256) {
        int n  = item / (HWN/4);
        int p4 = item - n * (HWN/4);
        const float4* f4 = (const float4*)(feat + (size_t)n * CC * HWN);

        float c0[4] = {0,0,0,0}, c1[4] = {0,0,0,0};
        float s0[4] = {0,0,0,0}, s1[4] = {0,0,0,0}, pv[4] = {0,0,0,0};
#pragma unroll 16
        for (int c = 0; c < CC; c++) {
            float4 v = __ldg(&f4[(size_t)c * (HWN/4) + p4]);
            float a0 = swc0[c], a1 = swc1[c], b0 = sws0[c], b1 = sws1[c], pw = swp[c];
            c0[0] = fmaf(v.x, a0, c0[0]); c0[1] = fmaf(v.y, a0, c0[1]);
            c0[2] = fmaf(v.z, a0, c0[2]); c0[3] = fmaf(v.w, a0, c0[3]);
            c1[0] = fmaf(v.x, a1, c1[0]); c1[1] = fmaf(v.y, a1, c1[1]);
            c1[2] = fmaf(v.z, a1, c1[2]); c1[3] = fmaf(v.w, a1, c1[3]);
            s0[0] = fmaf(v.x, b0, s0[0]); s0[1] = fmaf(v.y, b0, s0[1]);
            s0[2] = fmaf(v.z, b0, s0[2]); s0[3] = fmaf(v.w, b0, s0[3]);
            s1[0] = fmaf(v.x, b1, s1[0]); s1[1] = fmaf(v.y, b1, s1[1]);
            s1[2] = fmaf(v.z, b1, s1[2]); s1[3] = fmaf(v.w, b1, s1[3]);
            pv[0] = fmaf(v.x, pw, pv[0]); pv[1] = fmaf(v.y, pw, pv[1]);
            pv[2] = fmaf(v.z, pw, pv[2]); pv[3] = fmaf(v.w, pw, pv[3]);
        }

        float4 av, bv;
        float* avp = &av.x; float* bvp = &bv.x;
#pragma unroll
        for (int m = 0; m < 4; m++) {
            int idx = p4 * 4 + m;
            float st0 = fmaxf(s0[m], 0.f), st1 = fmaxf(s1[m], 0.f);
            float pr = 1.f / (1.f + expf(-pv[m]));
            int i = idx / WW, j = idx - (idx / WW) * WW;
            float th = fminf(rintf((float)i + c0[m] * st0), (float)(WW - 1));
            float tw = fminf(rintf((float)j + c1[m] * st1), (float)(WW - 1));
            int tt = (int)(th * (float)WW + tw);
            tt %= HWN; if (tt < 0) tt += HWN;    // python-style mod
            atomicMax(&g_winner[n * HWN + tt], idx + 1);
            float q = 1.f - pr;
            avp[m] = pr + q * q;
            bvp[m] = pr * q;
        }
        ((float4*)g_a)[(size_t)n * (HWN/4) + p4] = av;
        ((float4*)g_b)[(size_t)n * (HWN/4) + p4] = bv;
    }
}

// ---------------------------------------------------------------------------
// Pass B: mirror-tile pairs + cp.async double-buffered channel pipeline.
// blockIdx.x = triangular pair index (by<=bx), z = n*2 + channel-half.
//   A: rows [aR..) x cols [aC..)    B: mirror (skipped when diagonal)
// Staged tile A is f-source for A and gather source for B (and vice versa).
// Tiles stored with float4-slot XOR swizzle: 16B-aligned for cp.async AND
// conflict-free for both row-major f-reads and transpose-pattern gathers.
// ---------------------------------------------------------------------------
__global__ void __launch_bounds__(256) pass_b(const float* __restrict__ feat,
                                              float* __restrict__ out) {
    __shared__ float sbuf[2][NSTG][2][TS*TS];   // [buf][stage-ch][tile A/B][swz]

    // decode triangular pair index: tidx = bx*(bx+1)/2 + by, by<=bx
    int tidx = blockIdx.x;
    int bx = (int)((sqrtf(8.f * (float)tidx + 1.f) - 1.f) * 0.5f);
    while (bx * (bx + 1) / 2 > tidx) bx--;          // fix float rounding
    while ((bx + 1) * (bx + 2) / 2 <= tidx) bx++;
    int by = tidx - bx * (bx + 1) / 2;
    bool diag = (bx == by);

    int zc = blockIdx.z;
    int n = zc >> 1;
    int cbase = (zc & 1) * CPB;

    int aR = by * TS, aC = bx * TS;
    int ah = min(TS, WW - aR), aw = min(TS, WW - aC);   // 32 or 16

    int tid = threadIdx.x;
    int trow = tid >> 3, tq = tid & 7, tc0 = tq * 4;
    int slotoff = trow * 32 + ((tq ^ (trow >> 2)) & 7) * 4;

    const float* fb = feat + (size_t)n * CC * HWN;
    float*       ob = out  + (size_t)n * CC * HWN;
    const int*   wn = g_winner + n * HWN;
    const float* ga = g_a + n * HWN;
    const float* gb = g_b + n * HWN;

    bool aval = (trow < ah) && (tc0 < aw);
    bool bval = (!diag) && (trow < aw) && (tc0 < ah);

    // ---- metadata (registers), read-only ----
    int gA[4]; float4 cAa, cAb;
    if (aval) {
        int idx = (aR + trow) * WW + aC + tc0;
        int4 w4 = *(const int4*)(wn + idx);
        cAa = *(const float4*)(ga + idx);
        cAb = *(const float4*)(gb + idx);
        int wv[4] = {w4.x, w4.y, w4.z, w4.w};
#pragma unroll
        for (int m = 0; m < 4; m++) {
            int src = (wv[m] > 0) ? (wv[m] - 1) : (idx + m);
            int sh = src / WW, sw = src - sh * WW;       // sampled = feat[sw][sh]
            int lr = sw - aC, lc = sh - aR;              // into B region
            gA[m] = ((unsigned)lr < (unsigned)aw && (unsigned)lc < (unsigned)ah)
                    ? swz(lr, lc)
                    : (FAST_TAG | (sw * WW + sh));
        }
    }
    int gB[4]; float4 cBa, cBb;
    if (bval) {
        int idx = (aC + trow) * WW + aR + tc0;
        int4 w4 = *(const int4*)(wn + idx);
        cBa = *(const float4*)(ga + idx);
        cBb = *(const float4*)(gb + idx);
        int wv[4] = {w4.x, w4.y, w4.z, w4.w};
#pragma unroll
        for (int m = 0; m < 4; m++) {
            int src = (wv[m] > 0) ? (wv[m] - 1) : (idx + m);
            int sh = src / WW, sw = src - sh * WW;
            int lr = sw - aR, lc = sh - aC;              // into A region
            gB[m] = ((unsigned)lr < (unsigned)ah && (unsigned)lc < (unsigned)aw)
                    ? swz(lr, lc)
                    : (FAST_TAG | (sw * WW + sh));
        }
    }

    auto stage = [&](int g) {
        int b = g & 1;
#pragma unroll
        for (int s = 0; s < NSTG; s++) {
            const float* fp = fb + (size_t)(cbase + g * NSTG + s) * HWN;
            if (aval) cp16(&sbuf[b][s][0][slotoff], fp + (aR + trow) * WW + aC + tc0);
            if (bval) cp16(&sbuf[b][s][1][slotoff], fp + (aC + trow) * WW + aR + tc0);
        }
        asm volatile("cp.async.commit_group;");
    };

    stage(0); stage(1);

    for (int g = 0; g < NGRP; g++) {
        int b = g & 1;
        if (g < NGRP - 1) asm volatile("cp.async.wait_group 1;");
        else              asm volatile("cp.async.wait_group 0;");
        __syncthreads();

#pragma unroll
        for (int s = 0; s < NSTG; s++) {
            int ch = cbase + g * NSTG + s;
            const float* fp = fb + (size_t)ch * HWN;
            float*       op = ob + (size_t)ch * HWN;
            const float* tA = sbuf[b][s][0];
            const float* tB = sbuf[b][s][1];
            if (aval) {
                const float* gsrc = diag ? tA : tB;
                float4 f = *(const float4*)(tA + slotoff);
                const float* fx = &f.x;
                const float* ca = &cAa.x; const float* cb = &cAb.x;
                float4 o; float* ox = &o.x;
#pragma unroll
                for (int m = 0; m < 4; m++) {
                    int gi = gA[m];
                    float sval = (gi & FAST_TAG) ? __ldg(fp + (gi & (FAST_TAG-1)))
                                                 : gsrc[gi];
                    ox[m] = ca[m] * fx[m] + cb[m] * sval;
                }
                *(float4*)(op + (aR + trow) * WW + aC + tc0) = o;
            }
            if (bval) {
                float4 f = *(const float4*)(tB + slotoff);
                const float* fx = &f.x;
                const float* ca = &cBa.x; const float* cb = &cBb.x;
                float4 o; float* ox = &o.x;
#pragma unroll
                for (int m = 0; m < 4; m++) {
                    int gi = gB[m];
                    float sval = (gi & FAST_TAG) ? __ldg(fp + (gi & (FAST_TAG-1)))
                                                 : tA[gi];
                    ox[m] = ca[m] * fx[m] + cb[m] * sval;
                }
                *(float4*)(op + (aC + trow) * WW + aR + tc0) = o;
            }
        }
        __syncthreads();
        if (g + 2 < NGRP) stage(g + 2);
    }
}

extern "C" void kernel_launch(void* const* d_in, const int* in_sizes, int n_in,
                              void* d_out, int out_size) {
    const float* feat = (const float*)d_in[0];
    const float* wc   = (const float*)d_in[1];
    const float* ws   = (const float*)d_in[2];
    const float* wp   = (const float*)d_in[3];
    float* out = (float*)d_out;

    pass_a<<<PA_BLOCKS, 256>>>(feat, wc, ws, wp);
    pass_b<<<dim3(NPAIR, 1, NB * 2), 256>>>(feat, out);
    reset_kernel<<<NB*HWN/4/256, 256>>>();
}